// round 6
// baseline (speedup 1.0000x reference)
#include <cuda_runtime.h>
#include <cuda_bf16.h>
#include <math.h>

#define N_NODES 100000
#define D 128

// Scratch: ping-pong node-feature buffers (static __device__ per allocation rules)
__device__ float g_bufA[(size_t)N_NODES * D];
__device__ float g_bufB[(size_t)N_NODES * D];

// ---------------------------------------------------------------------------
// Zero a float buffer (grid-stride, float4)
// ---------------------------------------------------------------------------
__global__ void zero_kernel(float* __restrict__ buf, int n4) {
    int idx = blockIdx.x * blockDim.x + threadIdx.x;
    int stride = gridDim.x * blockDim.x;
    float4 z = make_float4(0.f, 0.f, 0.f, 0.f);
    for (int i = idx; i < n4; i += stride)
        reinterpret_cast<float4*>(buf)[i] = z;
}

// ---------------------------------------------------------------------------
// SpMM: out[row[e]] += val[e] * x[col[e]]   (one warp per edge, float4 lanes)
// ---------------------------------------------------------------------------
__global__ __launch_bounds__(256) void spmm_kernel(
    const int* __restrict__ erow, const int* __restrict__ ecol,
    const float* __restrict__ eval, const float* __restrict__ x,
    float* __restrict__ out, int nE)
{
    int gtid = blockIdx.x * blockDim.x + threadIdx.x;
    int e = gtid >> 5;
    int lane = gtid & 31;
    if (e >= nE) return;

    int r = __ldg(erow + e);
    int c = __ldg(ecol + e);
    float v = __ldg(eval + e);

    const float4 xv = *reinterpret_cast<const float4*>(x + (size_t)c * D + lane * 4);
    float a0 = xv.x * v, a1 = xv.y * v, a2 = xv.z * v, a3 = xv.w * v;

    float* dst = out + (size_t)r * D + lane * 4;
    asm volatile("red.global.add.v4.f32 [%0], {%1, %2, %3, %4};"
                 :: "l"(dst), "f"(a0), "f"(a1), "f"(a2), "f"(a3)
                 : "memory");
}

// ---------------------------------------------------------------------------
// C[M,128] = relu(A[M,128] @ W[128,128] + b)
// Block: 256 threads, tile 64 rows x 128 cols, per-thread 4x8 micro-tile.
// ---------------------------------------------------------------------------
#define BM 64
#define BK 32
#define AS_LD (BK + 1)

__global__ __launch_bounds__(256) void gemm_bias_relu_kernel(
    const float* __restrict__ A, const float* __restrict__ W,
    const float* __restrict__ bias, float* __restrict__ C, int M)
{
    __shared__ float As[BM * AS_LD];    // padded: kills bank conflicts on broadcast pairs
    __shared__ float Ws[BK * D];

    const int tid = threadIdx.x;
    const int tx = tid & 15;            // col group -> cols [tx*8, tx*8+8)
    const int ty = tid >> 4;            // row group -> rows [ty*4, ty*4+4)
    const int row0 = blockIdx.x * BM;

    float acc[4][8];
    #pragma unroll
    for (int i = 0; i < 4; i++)
        #pragma unroll
        for (int j = 0; j < 8; j++) acc[i][j] = 0.f;

    for (int k0 = 0; k0 < D; k0 += BK) {
        // Stage A tile [BM x BK] (row-major source, padded smem)
        #pragma unroll
        for (int i = 0; i < 2; i++) {
            int fid = tid + i * 256;        // 512 float4 loads total
            int m   = fid >> 3;             // 8 float4 per row of 32
            int kk  = (fid & 7) << 2;
            int gr  = row0 + m;
            float4 v = make_float4(0.f, 0.f, 0.f, 0.f);
            if (gr < M)
                v = *reinterpret_cast<const float4*>(A + (size_t)gr * D + k0 + kk);
            float* s = As + m * AS_LD + kk;
            s[0] = v.x; s[1] = v.y; s[2] = v.z; s[3] = v.w;
        }
        // Stage W tile [BK x 128]
        #pragma unroll
        for (int i = 0; i < 4; i++) {
            int fid = tid + i * 256;        // 1024 float4 loads total
            int k   = fid >> 5;
            int n4  = (fid & 31) << 2;
            *reinterpret_cast<float4*>(Ws + k * D + n4) =
                *reinterpret_cast<const float4*>(W + (size_t)(k0 + k) * D + n4);
        }
        __syncthreads();

        #pragma unroll
        for (int kk = 0; kk < BK; kk++) {
            float a[4];
            #pragma unroll
            for (int i = 0; i < 4; i++)
                a[i] = As[(ty * 4 + i) * AS_LD + kk];
            const float4 w0 = *reinterpret_cast<const float4*>(Ws + kk * D + tx * 8);
            const float4 w1 = *reinterpret_cast<const float4*>(Ws + kk * D + tx * 8 + 4);
            #pragma unroll
            for (int i = 0; i < 4; i++) {
                acc[i][0] += a[i] * w0.x;
                acc[i][1] += a[i] * w0.y;
                acc[i][2] += a[i] * w0.z;
                acc[i][3] += a[i] * w0.w;
                acc[i][4] += a[i] * w1.x;
                acc[i][5] += a[i] * w1.y;
                acc[i][6] += a[i] * w1.z;
                acc[i][7] += a[i] * w1.w;
            }
        }
        __syncthreads();
    }

    const float4 b0 = *reinterpret_cast<const float4*>(bias + tx * 8);
    const float4 b1 = *reinterpret_cast<const float4*>(bias + tx * 8 + 4);
    #pragma unroll
    for (int i = 0; i < 4; i++) {
        int gr = row0 + ty * 4 + i;
        if (gr >= M) continue;
        float4 o0, o1;
        o0.x = fmaxf(acc[i][0] + b0.x, 0.f);
        o0.y = fmaxf(acc[i][1] + b0.y, 0.f);
        o0.z = fmaxf(acc[i][2] + b0.z, 0.f);
        o0.w = fmaxf(acc[i][3] + b0.w, 0.f);
        o1.x = fmaxf(acc[i][4] + b1.x, 0.f);
        o1.y = fmaxf(acc[i][5] + b1.y, 0.f);
        o1.z = fmaxf(acc[i][6] + b1.z, 0.f);
        o1.w = fmaxf(acc[i][7] + b1.w, 0.f);
        *reinterpret_cast<float4*>(C + (size_t)gr * D + tx * 8)     = o0;
        *reinterpret_cast<float4*>(C + (size_t)gr * D + tx * 8 + 4) = o1;
    }
}

// ---------------------------------------------------------------------------
// out[n] = softplus(dot(H[n], Wout) + bout)  — one warp per row
// ---------------------------------------------------------------------------
__global__ __launch_bounds__(256) void head_kernel(
    const float* __restrict__ H, const float* __restrict__ Wout,
    const float* __restrict__ bout, float* __restrict__ out, int M)
{
    int gtid = blockIdx.x * blockDim.x + threadIdx.x;
    int r = gtid >> 5;
    int lane = gtid & 31;
    if (r >= M) return;

    const float4 h = *reinterpret_cast<const float4*>(H + (size_t)r * D + lane * 4);
    const float4 w = *reinterpret_cast<const float4*>(Wout + lane * 4);
    float s = h.x * w.x + h.y * w.y + h.z * w.z + h.w * w.w;
    #pragma unroll
    for (int o = 16; o > 0; o >>= 1)
        s += __shfl_xor_sync(0xFFFFFFFFu, s, o);
    if (lane == 0) {
        s += bout[0];
        // softplus = logaddexp(s, 0) = max(s,0) + log1p(exp(-|s|))
        out[r] = fmaxf(s, 0.f) + log1pf(expf(-fabsf(s)));
    }
}

// ---------------------------------------------------------------------------
// Launch
// ---------------------------------------------------------------------------
extern "C" void kernel_launch(void* const* d_in, const int* in_sizes, int n_in,
                              void* d_out, int out_size)
{
    const float* x     = (const float*)d_in[0];
    const int*   erow  = (const int*)  d_in[1];
    const int*   ecol  = (const int*)  d_in[2];
    const float* eval  = (const float*)d_in[3];
    const float* W1    = (const float*)d_in[4];
    const float* b1    = (const float*)d_in[5];
    const float* W2    = (const float*)d_in[6];
    const float* b2    = (const float*)d_in[7];
    const float* Wout  = (const float*)d_in[8];
    const float* bout  = (const float*)d_in[9];
    float* out = (float*)d_out;

    const int M  = in_sizes[0] / D;     // 100000
    const int nE = in_sizes[1];         // 1600000

    float* bufA;
    float* bufB;
    cudaGetSymbolAddress((void**)&bufA, g_bufA);
    cudaGetSymbolAddress((void**)&bufB, g_bufB);

    const int n4 = (M * D) / 4;
    const int zeroBlocks = 2048;
    const int spmmBlocks = (nE * 32 + 255) / 256;
    const int gemmBlocks = (M + BM - 1) / BM;
    const int headBlocks = (M * 32 + 255) / 256;

    // Layer 1: h = relu(spmm(x) @ W1 + b1)
    zero_kernel<<<zeroBlocks, 256>>>(bufA, n4);
    spmm_kernel<<<spmmBlocks, 256>>>(erow, ecol, eval, x, bufA, nE);
    gemm_bias_relu_kernel<<<gemmBlocks, 256>>>(bufA, W1, b1, bufB, M);

    // Layer 2: h = relu(spmm(h) @ W2 + b2)
    zero_kernel<<<zeroBlocks, 256>>>(bufA, n4);
    spmm_kernel<<<spmmBlocks, 256>>>(erow, ecol, eval, bufB, bufA, nE);
    gemm_bias_relu_kernel<<<gemmBlocks, 256>>>(bufA, W2, b2, bufB, M);

    // Final aggregation + head
    zero_kernel<<<zeroBlocks, 256>>>(bufA, n4);
    spmm_kernel<<<spmmBlocks, 256>>>(erow, ecol, eval, bufB, bufA, nE);
    head_kernel<<<headBlocks, 256>>>(bufA, Wout, bout, out, M);
}

// round 7
// speedup vs baseline: 1.0045x; 1.0045x over previous
#include <cuda_runtime.h>
#include <cuda_bf16.h>
#include <math.h>

#define N_NODES 100000
#define D 128

// Scratch: ping-pong node-feature buffers (static __device__ per allocation rules)
__device__ float g_bufA[(size_t)N_NODES * D];
__device__ float g_bufB[(size_t)N_NODES * D];

// ---------------------------------------------------------------------------
// Zero a float buffer (grid-stride, float4)
// ---------------------------------------------------------------------------
__global__ void zero_kernel(float* __restrict__ buf, int n4) {
    int idx = blockIdx.x * blockDim.x + threadIdx.x;
    int stride = gridDim.x * blockDim.x;
    float4 z = make_float4(0.f, 0.f, 0.f, 0.f);
    for (int i = idx; i < n4; i += stride)
        reinterpret_cast<float4*>(buf)[i] = z;
}

// ---------------------------------------------------------------------------
// SpMM: out[row[e]] += val[e] * x[col[e]]   (one warp per edge, float4 lanes)
// ---------------------------------------------------------------------------
__global__ __launch_bounds__(256) void spmm_kernel(
    const int* __restrict__ erow, const int* __restrict__ ecol,
    const float* __restrict__ eval, const float* __restrict__ x,
    float* __restrict__ out, int nE)
{
    int gtid = blockIdx.x * blockDim.x + threadIdx.x;
    int e = gtid >> 5;
    int lane = gtid & 31;
    if (e >= nE) return;

    int r = __ldg(erow + e);
    int c = __ldg(ecol + e);
    float v = __ldg(eval + e);

    const float4 xv = *reinterpret_cast<const float4*>(x + (size_t)c * D + lane * 4);
    float a0 = xv.x * v, a1 = xv.y * v, a2 = xv.z * v, a3 = xv.w * v;

    float* dst = out + (size_t)r * D + lane * 4;
    asm volatile("red.global.add.v4.f32 [%0], {%1, %2, %3, %4};"
                 :: "l"(dst), "f"(a0), "f"(a1), "f"(a2), "f"(a3)
                 : "memory");
}

// ---------------------------------------------------------------------------
// C[M,128] = relu(A[M,128] @ W[128,128] + b)
// Block: 256 threads, tile 64 rows x 128 cols, per-thread 4x8 micro-tile.
// ---------------------------------------------------------------------------
#define BM 64
#define BK 32
#define AS_LD (BK + 1)

__global__ __launch_bounds__(256) void gemm_bias_relu_kernel(
    const float* __restrict__ A, const float* __restrict__ W,
    const float* __restrict__ bias, float* __restrict__ C, int M)
{
    __shared__ float As[BM * AS_LD];    // padded: kills bank conflicts on broadcast pairs
    __shared__ float Ws[BK * D];

    const int tid = threadIdx.x;
    const int tx = tid & 15;            // col group -> cols [tx*8, tx*8+8)
    const int ty = tid >> 4;            // row group -> rows [ty*4, ty*4+4)
    const int row0 = blockIdx.x * BM;

    float acc[4][8];
    #pragma unroll
    for (int i = 0; i < 4; i++)
        #pragma unroll
        for (int j = 0; j < 8; j++) acc[i][j] = 0.f;

    for (int k0 = 0; k0 < D; k0 += BK) {
        // Stage A tile [BM x BK] (row-major source, padded smem)
        #pragma unroll
        for (int i = 0; i < 2; i++) {
            int fid = tid + i * 256;        // 512 float4 loads total
            int m   = fid >> 3;             // 8 float4 per row of 32
            int kk  = (fid & 7) << 2;
            int gr  = row0 + m;
            float4 v = make_float4(0.f, 0.f, 0.f, 0.f);
            if (gr < M)
                v = *reinterpret_cast<const float4*>(A + (size_t)gr * D + k0 + kk);
            float* s = As + m * AS_LD + kk;
            s[0] = v.x; s[1] = v.y; s[2] = v.z; s[3] = v.w;
        }
        // Stage W tile [BK x 128]
        #pragma unroll
        for (int i = 0; i < 4; i++) {
            int fid = tid + i * 256;        // 1024 float4 loads total
            int k   = fid >> 5;
            int n4  = (fid & 31) << 2;
            *reinterpret_cast<float4*>(Ws + k * D + n4) =
                *reinterpret_cast<const float4*>(W + (size_t)(k0 + k) * D + n4);
        }
        __syncthreads();

        #pragma unroll
        for (int kk = 0; kk < BK; kk++) {
            float a[4];
            #pragma unroll
            for (int i = 0; i < 4; i++)
                a[i] = As[(ty * 4 + i) * AS_LD + kk];
            const float4 w0 = *reinterpret_cast<const float4*>(Ws + kk * D + tx * 8);
            const float4 w1 = *reinterpret_cast<const float4*>(Ws + kk * D + tx * 8 + 4);
            #pragma unroll
            for (int i = 0; i < 4; i++) {
                acc[i][0] += a[i] * w0.x;
                acc[i][1] += a[i] * w0.y;
                acc[i][2] += a[i] * w0.z;
                acc[i][3] += a[i] * w0.w;
                acc[i][4] += a[i] * w1.x;
                acc[i][5] += a[i] * w1.y;
                acc[i][6] += a[i] * w1.z;
                acc[i][7] += a[i] * w1.w;
            }
        }
        __syncthreads();
    }

    const float4 b0 = *reinterpret_cast<const float4*>(bias + tx * 8);
    const float4 b1 = *reinterpret_cast<const float4*>(bias + tx * 8 + 4);
    #pragma unroll
    for (int i = 0; i < 4; i++) {
        int gr = row0 + ty * 4 + i;
        if (gr >= M) continue;
        float4 o0, o1;
        o0.x = fmaxf(acc[i][0] + b0.x, 0.f);
        o0.y = fmaxf(acc[i][1] + b0.y, 0.f);
        o0.z = fmaxf(acc[i][2] + b0.z, 0.f);
        o0.w = fmaxf(acc[i][3] + b0.w, 0.f);
        o1.x = fmaxf(acc[i][4] + b1.x, 0.f);
        o1.y = fmaxf(acc[i][5] + b1.y, 0.f);
        o1.z = fmaxf(acc[i][6] + b1.z, 0.f);
        o1.w = fmaxf(acc[i][7] + b1.w, 0.f);
        *reinterpret_cast<float4*>(C + (size_t)gr * D + tx * 8)     = o0;
        *reinterpret_cast<float4*>(C + (size_t)gr * D + tx * 8 + 4) = o1;
    }
}

// ---------------------------------------------------------------------------
// out[n] = softplus(dot(H[n], Wout) + bout)  — one warp per row
// ---------------------------------------------------------------------------
__global__ __launch_bounds__(256) void head_kernel(
    const float* __restrict__ H, const float* __restrict__ Wout,
    const float* __restrict__ bout, float* __restrict__ out, int M)
{
    int gtid = blockIdx.x * blockDim.x + threadIdx.x;
    int r = gtid >> 5;
    int lane = gtid & 31;
    if (r >= M) return;

    const float4 h = *reinterpret_cast<const float4*>(H + (size_t)r * D + lane * 4);
    const float4 w = *reinterpret_cast<const float4*>(Wout + lane * 4);
    float s = h.x * w.x + h.y * w.y + h.z * w.z + h.w * w.w;
    #pragma unroll
    for (int o = 16; o > 0; o >>= 1)
        s += __shfl_xor_sync(0xFFFFFFFFu, s, o);
    if (lane == 0) {
        s += bout[0];
        // softplus = logaddexp(s, 0) = max(s,0) + log1p(exp(-|s|))
        out[r] = fmaxf(s, 0.f) + log1pf(expf(-fabsf(s)));
    }
}

// ---------------------------------------------------------------------------
// Launch
// ---------------------------------------------------------------------------
extern "C" void kernel_launch(void* const* d_in, const int* in_sizes, int n_in,
                              void* d_out, int out_size)
{
    const float* x     = (const float*)d_in[0];
    const int*   erow  = (const int*)  d_in[1];
    const int*   ecol  = (const int*)  d_in[2];
    const float* eval  = (const float*)d_in[3];
    const float* W1    = (const float*)d_in[4];
    const float* b1    = (const float*)d_in[5];
    const float* W2    = (const float*)d_in[6];
    const float* b2    = (const float*)d_in[7];
    const float* Wout  = (const float*)d_in[8];
    const float* bout  = (const float*)d_in[9];
    float* out = (float*)d_out;

    const int M  = in_sizes[0] / D;     // 100000
    const int nE = in_sizes[1];         // 1600000

    float* bufA;
    float* bufB;
    cudaGetSymbolAddress((void**)&bufA, g_bufA);
    cudaGetSymbolAddress((void**)&bufB, g_bufB);

    const int n4 = (M * D) / 4;
    const int zeroBlocks = 2048;
    const int spmmBlocks = (nE * 32 + 255) / 256;
    const int gemmBlocks = (M + BM - 1) / BM;
    const int headBlocks = (M * 32 + 255) / 256;

    // Layer 1: h = relu(spmm(x) @ W1 + b1)
    zero_kernel<<<zeroBlocks, 256>>>(bufA, n4);
    spmm_kernel<<<spmmBlocks, 256>>>(erow, ecol, eval, x, bufA, nE);
    gemm_bias_relu_kernel<<<gemmBlocks, 256>>>(bufA, W1, b1, bufB, M);

    // Layer 2: h = relu(spmm(h) @ W2 + b2)
    zero_kernel<<<zeroBlocks, 256>>>(bufA, n4);
    spmm_kernel<<<spmmBlocks, 256>>>(erow, ecol, eval, bufB, bufA, nE);
    gemm_bias_relu_kernel<<<gemmBlocks, 256>>>(bufA, W2, b2, bufB, M);

    // Final aggregation + head
    zero_kernel<<<zeroBlocks, 256>>>(bufA, n4);
    spmm_kernel<<<spmmBlocks, 256>>>(erow, ecol, eval, bufB, bufA, nE);
    head_kernel<<<headBlocks, 256>>>(bufA, Wout, bout, out, M);
}